// round 2
// baseline (speedup 1.0000x reference)
#include <cuda_runtime.h>
#include <cuda_bf16.h>
#include <cstdint>

static constexpr int Bx = 4096;
static constexpr int D  = 512;
static constexpr int N  = 8192;
static constexpr float EPS = 1e-8f;

static constexpr int TILE = 128;       // square output tile
static constexpr int BK   = 64;        // k-chunk: 64 bf16 = 128B rows
static constexpr int NCH  = D / BK;    // 8
static constexpr int NT   = N / TILE;  // 64 tiles per dim
static constexpr int NTRI = NT * (NT + 1) / 2;  // 2080 blocks

static constexpr int STAGE_BYTES = 2 * TILE * BK * 2;  // A+B per stage = 32768
static constexpr int SMEM_TOTAL  = 2 * STAGE_BYTES;    // 65536

// scratch (device globals — no allocation allowed)
__device__ __align__(256) __nv_bfloat16 g_Zb[(size_t)N * D];  // normalized bf16 reps
__device__ float g_norms[N];
__device__ float g_pos[Bx];
__device__ float g_rowsum[N];

// ---------------------------------------------------------------------------
// Kernel 1: normalize rows of reps = [zjs; zis] -> bf16; save norms; zero rowsum
// ---------------------------------------------------------------------------
__global__ void __launch_bounds__(128) prep_kernel(const float* __restrict__ zis,
                                                   const float* __restrict__ zjs) {
    const int row = blockIdx.x;
    const int tid = threadIdx.x;
    const float* src = (row < Bx) ? (zjs + (size_t)row * D)
                                  : (zis + (size_t)(row - Bx) * D);
    float4 v = reinterpret_cast<const float4*>(src)[tid];
    float ss = v.x * v.x + v.y * v.y + v.z * v.z + v.w * v.w;
#pragma unroll
    for (int o = 16; o > 0; o >>= 1) ss += __shfl_xor_sync(0xffffffffu, ss, o);
    __shared__ float ws[4];
    if ((tid & 31) == 0) ws[tid >> 5] = ss;
    __syncthreads();
    float tot = ws[0] + ws[1] + ws[2] + ws[3];
    float nrm = fmaxf(sqrtf(tot), EPS);
    if (tid == 0) { g_norms[row] = nrm; g_rowsum[row] = 0.0f; }
    float inv = 1.0f / nrm;
    __nv_bfloat162 p0 = __floats2bfloat162_rn(v.x * inv, v.y * inv);
    __nv_bfloat162 p1 = __floats2bfloat162_rn(v.z * inv, v.w * inv);
    uint2 st;
    st.x = *reinterpret_cast<uint32_t*>(&p0);
    st.y = *reinterpret_cast<uint32_t*>(&p1);
    *reinterpret_cast<uint2*>(&g_Zb[(size_t)row * D + tid * 4]) = st;
}

// ---------------------------------------------------------------------------
// Kernel 2: positive logits fp32: pos[i] = dot(zis_i, zjs_i)/(n_i n_j) / TEMP
// ---------------------------------------------------------------------------
__global__ void __launch_bounds__(128) pos_kernel(const float* __restrict__ zis,
                                                  const float* __restrict__ zjs) {
    const int i = blockIdx.x;
    const int tid = threadIdx.x;
    float4 a = reinterpret_cast<const float4*>(zis + (size_t)i * D)[tid];
    float4 b = reinterpret_cast<const float4*>(zjs + (size_t)i * D)[tid];
    float d = a.x * b.x + a.y * b.y + a.z * b.z + a.w * b.w;
#pragma unroll
    for (int o = 16; o > 0; o >>= 1) d += __shfl_xor_sync(0xffffffffu, d, o);
    __shared__ float ws[4];
    if ((tid & 31) == 0) ws[tid >> 5] = d;
    __syncthreads();
    if (tid == 0) {
        float tot = ws[0] + ws[1] + ws[2] + ws[3];
        g_pos[i] = tot / (g_norms[i] * g_norms[Bx + i]) * 2.0f;  // 1/TEMP = 2
    }
}

// ---------------------------------------------------------------------------
// GEMM kernel: HMMA m16n8k16 bf16, 128x128 tile, triangular grid (symmetry).
// Off-diagonal tiles accumulate row sums AND column sums (transpose rows).
// ---------------------------------------------------------------------------
__device__ __forceinline__ void ldmatrix_x4(uint32_t* r, uint32_t addr) {
    asm volatile(
        "ldmatrix.sync.aligned.m8n8.x4.shared.b16 {%0, %1, %2, %3}, [%4];"
        : "=r"(r[0]), "=r"(r[1]), "=r"(r[2]), "=r"(r[3]) : "r"(addr));
}

__device__ __forceinline__ void mma16816(float* d, const uint32_t* a, const uint32_t* b) {
    asm volatile(
        "mma.sync.aligned.m16n8k16.row.col.f32.bf16.bf16.f32 "
        "{%0, %1, %2, %3}, {%4, %5, %6, %7}, {%8, %9}, {%0, %1, %2, %3};"
        : "+f"(d[0]), "+f"(d[1]), "+f"(d[2]), "+f"(d[3])
        : "r"(a[0]), "r"(a[1]), "r"(a[2]), "r"(a[3]), "r"(b[0]), "r"(b[1]));
}

__device__ __forceinline__ float exp2dot(float dot) {
    // exp(2*dot) = (poly6(dot/4))^8, |dot/4| <= ~0.26 -> Taylor error ~1e-8
    float r = dot * 0.25f;
    float p = 1.0f / 720.0f;
    p = fmaf(p, r, 1.0f / 120.0f);
    p = fmaf(p, r, 1.0f / 24.0f);
    p = fmaf(p, r, 1.0f / 6.0f);
    p = fmaf(p, r, 0.5f);
    p = fmaf(p, r, 1.0f);
    p = fmaf(p, r, 1.0f);
    p = p * p; p = p * p; p = p * p;
    return p;
}

__global__ void __launch_bounds__(256) gemm_kernel() {
    extern __shared__ __align__(1024) char dynsmem[];
    const uint32_t smem_base = (uint32_t)__cvta_generic_to_shared(dynsmem);
    const int tid = threadIdx.x;
    const int wid = tid >> 5, lid = tid & 31;
    const int wm = wid & 3;        // 4 warps along M (32 rows each)
    const int wn = wid >> 2;       // 2 warps along N (64 cols each)

    // triangular tile decode: tiles (I, J) with J <= I
    int t = blockIdx.x;
    int I = (int)((sqrtf(8.0f * (float)t + 1.0f) - 1.0f) * 0.5f);
    while ((I + 1) * (I + 2) / 2 <= t) ++I;
    while (I * (I + 1) / 2 > t) --I;
    const int J = t - I * (I + 1) / 2;
    const int rowBase = I * TILE;
    const int colBase = J * TILE;
    const bool diag = (I == J);

    float acc[2][8][4];
#pragma unroll
    for (int mi = 0; mi < 2; ++mi)
#pragma unroll
        for (int nf = 0; nf < 8; ++nf)
#pragma unroll
            for (int q = 0; q < 4; ++q) acc[mi][nf][q] = 0.0f;

    // cp.async tile loader: rows of 64 bf16 (128B = 8 x 16B chunks), xor swizzle
    auto load_stage = [&](int stage, int c) {
        const uint32_t Ab = smem_base + stage * STAGE_BYTES;
        const uint32_t Bb = Ab + TILE * BK * 2;
        const int k0 = c * BK;
#pragma unroll
        for (int it = 0; it < 4; ++it) {
            int idx = tid + it * 256;         // 0..1023
            int r = idx >> 3, seg = idx & 7;
            const __nv_bfloat16* src = &g_Zb[(size_t)(rowBase + r) * D + k0 + seg * 8];
            uint32_t dst = Ab + r * 128 + ((seg ^ (r & 7)) << 4);
            asm volatile("cp.async.cg.shared.global [%0], [%1], 16;"
                         :: "r"(dst), "l"(src));
        }
#pragma unroll
        for (int it = 0; it < 4; ++it) {
            int idx = tid + it * 256;
            int r = idx >> 3, seg = idx & 7;
            const __nv_bfloat16* src = &g_Zb[(size_t)(colBase + r) * D + k0 + seg * 8];
            uint32_t dst = Bb + r * 128 + ((seg ^ (r & 7)) << 4);
            asm volatile("cp.async.cg.shared.global [%0], [%1], 16;"
                         :: "r"(dst), "l"(src));
        }
        asm volatile("cp.async.commit_group;");
    };

    auto compute_stage = [&](int stage) {
        const uint32_t Ab = smem_base + stage * STAGE_BYTES;
        const uint32_t Bb = Ab + TILE * BK * 2;
#pragma unroll
        for (int ks = 0; ks < 4; ++ks) {
            const int k0 = ks * 16;  // bf16 index
            uint32_t a[2][4];
#pragma unroll
            for (int mi = 0; mi < 2; ++mi) {
                int row = wm * 32 + mi * 16 + (lid & 7) + ((lid >> 3) & 1) * 8;
                int kch = (k0 + (lid >> 4) * 8) >> 3;
                uint32_t addr = Ab + row * 128 + (((kch ^ (row & 7))) << 4);
                ldmatrix_x4(a[mi], addr);
            }
            uint32_t b[8][2];
#pragma unroll
            for (int np = 0; np < 4; ++np) {
                int row = wn * 64 + np * 16 + (lid & 7) + (lid >> 4) * 8;
                int kch = (k0 + ((lid >> 3) & 1) * 8) >> 3;
                uint32_t addr = Bb + row * 128 + (((kch ^ (row & 7))) << 4);
                uint32_t rr[4];
                ldmatrix_x4(rr, addr);
                b[np * 2][0] = rr[0]; b[np * 2][1] = rr[1];
                b[np * 2 + 1][0] = rr[2]; b[np * 2 + 1][1] = rr[3];
            }
#pragma unroll
            for (int mi = 0; mi < 2; ++mi)
#pragma unroll
                for (int nf = 0; nf < 8; ++nf)
                    mma16816(acc[mi][nf], a[mi], b[nf]);
        }
    };

    load_stage(0, 0);
    for (int c = 0; c < NCH; ++c) {
        const int cur = c & 1;
        if (c + 1 < NCH) load_stage(cur ^ 1, c + 1);
        if (c + 1 < NCH) asm volatile("cp.async.wait_group 1;");
        else             asm volatile("cp.async.wait_group 0;");
        __syncthreads();
        compute_stage(cur);
        __syncthreads();
    }

    // ---- epilogue: exp + row sums (+ col sums for off-diagonal tiles) ----
    float rsum[2][2] = {{0.f, 0.f}, {0.f, 0.f}};
    float csum[8][2];
#pragma unroll
    for (int nf = 0; nf < 8; ++nf) { csum[nf][0] = 0.f; csum[nf][1] = 0.f; }

#pragma unroll
    for (int mi = 0; mi < 2; ++mi) {
        const int r0 = rowBase + wm * 32 + mi * 16 + (lid >> 2);
#pragma unroll
        for (int nf = 0; nf < 8; ++nf) {
            const int c0 = colBase + wn * 64 + nf * 8 + (lid & 3) * 2;
            float e0 = exp2dot(acc[mi][nf][0]);
            float e1 = exp2dot(acc[mi][nf][1]);
            float e2 = exp2dot(acc[mi][nf][2]);
            float e3 = exp2dot(acc[mi][nf][3]);
            if (diag) {  // mask self-similarity
                if (c0 == r0)         e0 = 0.f;
                if (c0 + 1 == r0)     e1 = 0.f;
                if (c0 == r0 + 8)     e2 = 0.f;
                if (c0 + 1 == r0 + 8) e3 = 0.f;
            }
            rsum[mi][0] += e0 + e1;
            rsum[mi][1] += e2 + e3;
            csum[nf][0] += e0 + e2;
            csum[nf][1] += e1 + e3;
        }
    }

    // row sums: reduce over lanes sharing a row (lid&3), lane%4==0 commits
#pragma unroll
    for (int mi = 0; mi < 2; ++mi)
#pragma unroll
        for (int rp = 0; rp < 2; ++rp) {
            float v = rsum[mi][rp];
            v += __shfl_xor_sync(0xffffffffu, v, 1);
            v += __shfl_xor_sync(0xffffffffu, v, 2);
            if ((lid & 3) == 0) {
                int grow = rowBase + wm * 32 + mi * 16 + (lid >> 2) + rp * 8;
                atomicAdd(&g_rowsum[grow], v);
            }
        }

    // col sums (transpose rows), off-diagonal tiles only
    if (!diag) {
#pragma unroll
        for (int nf = 0; nf < 8; ++nf)
#pragma unroll
            for (int e = 0; e < 2; ++e) {
                float v = csum[nf][e];
                v += __shfl_xor_sync(0xffffffffu, v, 4);
                v += __shfl_xor_sync(0xffffffffu, v, 8);
                v += __shfl_xor_sync(0xffffffffu, v, 16);
                if (lid < 4) {
                    int gcol = colBase + wn * 64 + nf * 8 + lid * 2 + e;
                    atomicAdd(&g_rowsum[gcol], v);
                }
            }
    }
}

// ---------------------------------------------------------------------------
// finalize: loss = mean_i( log(rowsum_i) - pos[i mod B] )
// ---------------------------------------------------------------------------
__global__ void __launch_bounds__(256) finalize_kernel(float* __restrict__ out) {
    const int tid = threadIdx.x;
    float acc = 0.0f;
    for (int i = tid; i < N; i += 256)
        acc += logf(g_rowsum[i]) - g_pos[i & (Bx - 1)];
#pragma unroll
    for (int o = 16; o > 0; o >>= 1) acc += __shfl_xor_sync(0xffffffffu, acc, o);
    __shared__ float ws[8];
    if ((tid & 31) == 0) ws[tid >> 5] = acc;
    __syncthreads();
    if (tid == 0) {
        float tot = 0.0f;
#pragma unroll
        for (int w = 0; w < 8; ++w) tot += ws[w];
        out[0] = tot / (float)N;
    }
}

extern "C" void kernel_launch(void* const* d_in, const int* in_sizes, int n_in,
                              void* d_out, int out_size) {
    const float* zis = (const float*)d_in[0];
    const float* zjs = (const float*)d_in[1];
    float* out = (float*)d_out;
    cudaFuncSetAttribute(gemm_kernel,
                         cudaFuncAttributeMaxDynamicSharedMemorySize, SMEM_TOTAL);
    prep_kernel<<<N, 128>>>(zis, zjs);
    pos_kernel<<<Bx, 128>>>(zis, zjs);
    gemm_kernel<<<NTRI, 256, SMEM_TOTAL>>>();
    finalize_kernel<<<1, 256>>>(out);
}

// round 4
// speedup vs baseline: 1.0628x; 1.0628x over previous
#include <cuda_runtime.h>
#include <cuda_bf16.h>
#include <cstdint>

static constexpr int Bx = 4096;
static constexpr int D  = 512;
static constexpr int N  = 8192;
static constexpr float EPS = 1e-8f;

static constexpr int TILE = 128;       // square output tile
static constexpr int BK   = 64;        // k-chunk: 64 bf16 = 128B rows
static constexpr int NCH  = D / BK;    // 8
static constexpr int NT   = N / TILE;  // 64 tiles per dim
static constexpr int NTRI = NT * (NT + 1) / 2;  // 2080 blocks

static constexpr int STAGE_BYTES = 2 * TILE * BK * 2;  // A+B per stage = 32768
static constexpr int SMEM_TOTAL  = 2 * STAGE_BYTES;    // 65536

// scratch (device globals — no allocation allowed)
__device__ __align__(256) __nv_bfloat16 g_Zb[(size_t)N * D];  // normalized bf16 reps
__device__ float g_pos[Bx];
__device__ float g_rowsum[N];

// ---------------------------------------------------------------------------
// Kernel 1 (merged prep+pos): block i loads zis_i and zjs_i once.
//   reps row i      = zjs_i / ||zjs_i||
//   reps row Bx + i = zis_i / ||zis_i||
//   pos[i] = dot(zis_i, zjs_i) / (||zis_i|| ||zjs_i||) / TEMP
// Also zeroes g_rowsum rows i and Bx+i (graph replays need fresh zeros).
// ---------------------------------------------------------------------------
__global__ void __launch_bounds__(128) prep_kernel(const float* __restrict__ zis,
                                                   const float* __restrict__ zjs) {
    const int i = blockIdx.x;
    const int tid = threadIdx.x;
    float4 a = reinterpret_cast<const float4*>(zis + (size_t)i * D)[tid];
    float4 b = reinterpret_cast<const float4*>(zjs + (size_t)i * D)[tid];
    float sa = a.x * a.x + a.y * a.y + a.z * a.z + a.w * a.w;
    float sb = b.x * b.x + b.y * b.y + b.z * b.z + b.w * b.w;
    float dd = a.x * b.x + a.y * b.y + a.z * b.z + a.w * b.w;
#pragma unroll
    for (int o = 16; o > 0; o >>= 1) {
        sa += __shfl_xor_sync(0xffffffffu, sa, o);
        sb += __shfl_xor_sync(0xffffffffu, sb, o);
        dd += __shfl_xor_sync(0xffffffffu, dd, o);
    }
    __shared__ float wsa[4], wsb[4], wsd[4];
    if ((tid & 31) == 0) {
        wsa[tid >> 5] = sa; wsb[tid >> 5] = sb; wsd[tid >> 5] = dd;
    }
    __syncthreads();
    const float ta = wsa[0] + wsa[1] + wsa[2] + wsa[3];
    const float tb = wsb[0] + wsb[1] + wsb[2] + wsb[3];
    const float na = fmaxf(sqrtf(ta), EPS);
    const float nb = fmaxf(sqrtf(tb), EPS);
    if (tid == 0) {
        const float td = wsd[0] + wsd[1] + wsd[2] + wsd[3];
        g_pos[i] = td / (na * nb) * 2.0f;  // 1/TEMP = 2
        g_rowsum[i] = 0.0f;
        g_rowsum[Bx + i] = 0.0f;
    }
    const float ia = 1.0f / na, ib = 1.0f / nb;
    // row i = zjs_i / nb
    {
        __nv_bfloat162 p0 = __floats2bfloat162_rn(b.x * ib, b.y * ib);
        __nv_bfloat162 p1 = __floats2bfloat162_rn(b.z * ib, b.w * ib);
        uint2 st;
        st.x = *reinterpret_cast<uint32_t*>(&p0);
        st.y = *reinterpret_cast<uint32_t*>(&p1);
        *reinterpret_cast<uint2*>(&g_Zb[(size_t)i * D + tid * 4]) = st;
    }
    // row Bx+i = zis_i / na
    {
        __nv_bfloat162 p0 = __floats2bfloat162_rn(a.x * ia, a.y * ia);
        __nv_bfloat162 p1 = __floats2bfloat162_rn(a.z * ia, a.w * ia);
        uint2 st;
        st.x = *reinterpret_cast<uint32_t*>(&p0);
        st.y = *reinterpret_cast<uint32_t*>(&p1);
        *reinterpret_cast<uint2*>(&g_Zb[(size_t)(Bx + i) * D + tid * 4]) = st;
    }
}

// ---------------------------------------------------------------------------
// GEMM kernel: HMMA m16n8k16 bf16, 128x128 tile, triangular grid (symmetry).
// Off-diagonal tiles accumulate row sums AND column sums (transpose rows).
// ---------------------------------------------------------------------------
__device__ __forceinline__ void ldmatrix_x4(uint32_t* r, uint32_t addr) {
    asm volatile(
        "ldmatrix.sync.aligned.m8n8.x4.shared.b16 {%0, %1, %2, %3}, [%4];"
        : "=r"(r[0]), "=r"(r[1]), "=r"(r[2]), "=r"(r[3]) : "r"(addr));
}

__device__ __forceinline__ void mma16816(float* d, const uint32_t* a, const uint32_t* b) {
    asm volatile(
        "mma.sync.aligned.m16n8k16.row.col.f32.bf16.bf16.f32 "
        "{%0, %1, %2, %3}, {%4, %5, %6, %7}, {%8, %9}, {%0, %1, %2, %3};"
        : "+f"(d[0]), "+f"(d[1]), "+f"(d[2]), "+f"(d[3])
        : "r"(a[0]), "r"(a[1]), "r"(a[2]), "r"(a[3]), "r"(b[0]), "r"(b[1]));
}

__device__ __forceinline__ float exp2dot(float dot) {
    // exp(2*dot) = (poly6(dot/4))^8, |dot/4| <= ~0.26 -> Taylor error ~1e-8
    float r = dot * 0.25f;
    float p = 1.0f / 720.0f;
    p = fmaf(p, r, 1.0f / 120.0f);
    p = fmaf(p, r, 1.0f / 24.0f);
    p = fmaf(p, r, 1.0f / 6.0f);
    p = fmaf(p, r, 0.5f);
    p = fmaf(p, r, 1.0f);
    p = fmaf(p, r, 1.0f);
    p = p * p; p = p * p; p = p * p;
    return p;
}

__global__ void __launch_bounds__(256) gemm_kernel() {
    extern __shared__ __align__(1024) char dynsmem[];
    const uint32_t smem_base = (uint32_t)__cvta_generic_to_shared(dynsmem);
    const int tid = threadIdx.x;
    const int wid = tid >> 5, lid = tid & 31;
    const int wm = wid & 3;        // 4 warps along M (32 rows each)
    const int wn = wid >> 2;       // 2 warps along N (64 cols each)

    // triangular tile decode: tiles (I, J) with J <= I
    int t = blockIdx.x;
    int I = (int)((sqrtf(8.0f * (float)t + 1.0f) - 1.0f) * 0.5f);
    while ((I + 1) * (I + 2) / 2 <= t) ++I;
    while (I * (I + 1) / 2 > t) --I;
    const int J = t - I * (I + 1) / 2;
    const int rowBase = I * TILE;
    const int colBase = J * TILE;
    const bool diag = (I == J);

    float acc[2][8][4];
#pragma unroll
    for (int mi = 0; mi < 2; ++mi)
#pragma unroll
        for (int nf = 0; nf < 8; ++nf)
#pragma unroll
            for (int q = 0; q < 4; ++q) acc[mi][nf][q] = 0.0f;

    // cp.async tile loader: rows of 64 bf16 (128B = 8 x 16B chunks), xor swizzle
    auto load_stage = [&](int stage, int c) {
        const uint32_t Ab = smem_base + stage * STAGE_BYTES;
        const uint32_t Bb = Ab + TILE * BK * 2;
        const int k0 = c * BK;
#pragma unroll
        for (int it = 0; it < 4; ++it) {
            int idx = tid + it * 256;         // 0..1023
            int r = idx >> 3, seg = idx & 7;
            const __nv_bfloat16* src = &g_Zb[(size_t)(rowBase + r) * D + k0 + seg * 8];
            uint32_t dst = Ab + r * 128 + ((seg ^ (r & 7)) << 4);
            asm volatile("cp.async.cg.shared.global [%0], [%1], 16;"
                         :: "r"(dst), "l"(src));
        }
#pragma unroll
        for (int it = 0; it < 4; ++it) {
            int idx = tid + it * 256;
            int r = idx >> 3, seg = idx & 7;
            const __nv_bfloat16* src = &g_Zb[(size_t)(colBase + r) * D + k0 + seg * 8];
            uint32_t dst = Bb + r * 128 + ((seg ^ (r & 7)) << 4);
            asm volatile("cp.async.cg.shared.global [%0], [%1], 16;"
                         :: "r"(dst), "l"(src));
        }
        asm volatile("cp.async.commit_group;");
    };

    auto compute_stage = [&](int stage) {
        const uint32_t Ab = smem_base + stage * STAGE_BYTES;
        const uint32_t Bb = Ab + TILE * BK * 2;
#pragma unroll
        for (int ks = 0; ks < 4; ++ks) {
            const int k0 = ks * 16;  // bf16 index
            uint32_t a[2][4];
#pragma unroll
            for (int mi = 0; mi < 2; ++mi) {
                int row = wm * 32 + mi * 16 + (lid & 7) + ((lid >> 3) & 1) * 8;
                int kch = (k0 + (lid >> 4) * 8) >> 3;
                uint32_t addr = Ab + row * 128 + (((kch ^ (row & 7))) << 4);
                ldmatrix_x4(a[mi], addr);
            }
            uint32_t b[8][2];
#pragma unroll
            for (int np = 0; np < 4; ++np) {
                int row = wn * 64 + np * 16 + (lid & 7) + (lid >> 4) * 8;
                int kch = (k0 + ((lid >> 3) & 1) * 8) >> 3;
                uint32_t addr = Bb + row * 128 + (((kch ^ (row & 7))) << 4);
                uint32_t rr[4];
                ldmatrix_x4(rr, addr);
                b[np * 2][0] = rr[0]; b[np * 2][1] = rr[1];
                b[np * 2 + 1][0] = rr[2]; b[np * 2 + 1][1] = rr[3];
            }
#pragma unroll
            for (int mi = 0; mi < 2; ++mi)
#pragma unroll
                for (int nf = 0; nf < 8; ++nf)
                    mma16816(acc[mi][nf], a[mi], b[nf]);
        }
    };

    load_stage(0, 0);
    for (int c = 0; c < NCH; ++c) {
        const int cur = c & 1;
        if (c + 1 < NCH) load_stage(cur ^ 1, c + 1);
        if (c + 1 < NCH) asm volatile("cp.async.wait_group 1;");
        else             asm volatile("cp.async.wait_group 0;");
        __syncthreads();
        compute_stage(cur);
        __syncthreads();
    }

    // ---- epilogue: exp + row sums (+ col sums for off-diagonal tiles) ----
    float rsum[2][2] = {{0.f, 0.f}, {0.f, 0.f}};
    float csum[8][2];
#pragma unroll
    for (int nf = 0; nf < 8; ++nf) { csum[nf][0] = 0.f; csum[nf][1] = 0.f; }

#pragma unroll
    for (int mi = 0; mi < 2; ++mi) {
        const int r0 = rowBase + wm * 32 + mi * 16 + (lid >> 2);
#pragma unroll
        for (int nf = 0; nf < 8; ++nf) {
            const int c0 = colBase + wn * 64 + nf * 8 + (lid & 3) * 2;
            float e0 = exp2dot(acc[mi][nf][0]);
            float e1 = exp2dot(acc[mi][nf][1]);
            float e2 = exp2dot(acc[mi][nf][2]);
            float e3 = exp2dot(acc[mi][nf][3]);
            if (diag) {  // mask self-similarity
                if (c0 == r0)         e0 = 0.f;
                if (c0 + 1 == r0)     e1 = 0.f;
                if (c0 == r0 + 8)     e2 = 0.f;
                if (c0 + 1 == r0 + 8) e3 = 0.f;
            }
            rsum[mi][0] += e0 + e1;
            rsum[mi][1] += e2 + e3;
            csum[nf][0] += e0 + e2;
            csum[nf][1] += e1 + e3;
        }
    }

    // row sums: reduce over lanes sharing a row (lid&3), lane%4==0 commits
#pragma unroll
    for (int mi = 0; mi < 2; ++mi)
#pragma unroll
        for (int rp = 0; rp < 2; ++rp) {
            float v = rsum[mi][rp];
            v += __shfl_xor_sync(0xffffffffu, v, 1);
            v += __shfl_xor_sync(0xffffffffu, v, 2);
            if ((lid & 3) == 0) {
                int grow = rowBase + wm * 32 + mi * 16 + (lid >> 2) + rp * 8;
                atomicAdd(&g_rowsum[grow], v);
            }
        }

    // col sums (transpose rows), off-diagonal tiles only
    if (!diag) {
#pragma unroll
        for (int nf = 0; nf < 8; ++nf)
#pragma unroll
            for (int e = 0; e < 2; ++e) {
                float v = csum[nf][e];
                v += __shfl_xor_sync(0xffffffffu, v, 4);
                v += __shfl_xor_sync(0xffffffffu, v, 8);
                v += __shfl_xor_sync(0xffffffffu, v, 16);
                if (lid < 4) {
                    int gcol = colBase + wn * 64 + nf * 8 + lid * 2 + e;
                    atomicAdd(&g_rowsum[gcol], v);
                }
            }
    }
}

// ---------------------------------------------------------------------------
// finalize: loss = mean_i( log(rowsum_i) - pos[i mod B] ), 1024 threads
// ---------------------------------------------------------------------------
__global__ void __launch_bounds__(1024) finalize_kernel(float* __restrict__ out) {
    const int tid = threadIdx.x;
    float acc = 0.0f;
#pragma unroll
    for (int it = 0; it < N / 1024; ++it) {
        int i = tid + it * 1024;
        acc += __logf(g_rowsum[i]) - g_pos[i & (Bx - 1)];
    }
#pragma unroll
    for (int o = 16; o > 0; o >>= 1) acc += __shfl_xor_sync(0xffffffffu, acc, o);
    __shared__ float ws[32];
    if ((tid & 31) == 0) ws[tid >> 5] = acc;
    __syncthreads();
    if (tid < 32) {
        float v = ws[tid];
#pragma unroll
        for (int o = 16; o > 0; o >>= 1) v += __shfl_xor_sync(0xffffffffu, v, o);
        if (tid == 0) out[0] = v / (float)N;
    }
}

extern "C" void kernel_launch(void* const* d_in, const int* in_sizes, int n_in,
                              void* d_out, int out_size) {
    const float* zis = (const float*)d_in[0];
    const float* zjs = (const float*)d_in[1];
    float* out = (float*)d_out;
    cudaFuncSetAttribute(gemm_kernel,
                         cudaFuncAttributeMaxDynamicSharedMemorySize, SMEM_TOTAL);
    prep_kernel<<<Bx, 128>>>(zis, zjs);
    gemm_kernel<<<NTRI, 256, SMEM_TOTAL>>>();
    finalize_kernel<<<1, 1024>>>(out);
}